// round 4
// baseline (speedup 1.0000x reference)
#include <cuda_runtime.h>
#include <cuda_bf16.h>
#include <math.h>

#define N_NODES 10000
#define N_EDGES 160000
#define D 512
#define D_CAT 1024
#define LN_EPS 1e-5f

// ---------------- scratch (device globals; no runtime allocation) ----------
__device__ float g_agg[N_NODES * D];   // 20.48 MB  segment-sum result
__device__ float g_h1 [N_NODES * D];   // 20.48 MB  silu(cat @ W1 + b1)
__device__ float g_h2 [N_NODES * D];   // 20.48 MB  h1 @ W2 + b2
__device__ int   g_dst_is32;           // 1 if dst buffer is int32, 0 if int64

// ---------------- kernel 0: zero agg + flag --------------------------------
__global__ void zero_kernel() {
    int i = blockIdx.x * blockDim.x + threadIdx.x;
    int total = (N_NODES * D) / 4;
    if (i == 0) g_dst_is32 = 0;
    if (i < total) {
        reinterpret_cast<float4*>(g_agg)[i] = make_float4(0.f, 0.f, 0.f, 0.f);
    }
}

// ---------------- kernel 1: dtype probe ------------------------------------
// View dst as int32[160000] (fits the buffer whether the true dtype is
// int32 or int64). If true dtype is int64 (little-endian, values < 10000),
// every odd 32-bit word is zero. If int32, odd words are real dst values
// (uniform in [0,10000)) and some are nonzero with overwhelming probability.
__global__ void probe_dst_kernel(const int* __restrict__ dst32) {
    int i = blockIdx.x * blockDim.x + threadIdx.x;       // 0 .. 79999
    if (i < N_EDGES / 2) {
        if (dst32[2 * i + 1] != 0) g_dst_is32 = 1;       // racy all-write-1: fine
    }
}

// ---------------- kernel 2: fused efeat passthrough + scatter-add ----------
__global__ void scatter_kernel(const float4* __restrict__ efeat,
                               const void*  __restrict__ dst_raw,
                               float4*      __restrict__ out_efeat) {
    const int PER_EDGE = D / 4;                           // 128 float4 per edge
    long long i = (long long)blockIdx.x * blockDim.x + threadIdx.x;
    long long total = (long long)N_EDGES * PER_EDGE;
    if (i >= total) return;
    int e = (int)(i >> 7);          // i / 128
    int c = (int)(i & 127);         // i % 128

    float4 v = efeat[i];
    out_efeat[i] = v;               // passthrough (single read of efeat)

    int node;
    if (g_dst_is32) node = ((const int*)dst_raw)[e];
    else            node = (int)((const long long*)dst_raw)[e];

    float* base = &g_agg[(long long)node * D + c * 4];
    atomicAdd(base + 0, v.x);
    atomicAdd(base + 1, v.y);
    atomicAdd(base + 2, v.z);
    atomicAdd(base + 3, v.w);
}

// ---------------- tiled fp32 GEMM: C[M,N] = op(A) @ B + bias ---------------
// CONCAT: logical A row = [A0 row (512) | A1 row (512)], K = 1024
// SILU:   apply x*sigmoid(x) in epilogue
#define BM 64
#define BN 64
#define BK 16

template<bool CONCAT, bool SILU>
__global__ void gemm_kernel(const float* __restrict__ A0,
                            const float* __restrict__ A1,
                            const float* __restrict__ B,     // [K, N] row-major
                            const float* __restrict__ bias,  // [N]
                            float*       __restrict__ C,     // [M, N]
                            int M, int N, int K) {
    __shared__ float As[BK][BM];
    __shared__ float Bs[BK][BN];

    const int rowBase = blockIdx.y * BM;
    const int colBase = blockIdx.x * BN;
    const int tx = threadIdx.x;          // 0..15
    const int ty = threadIdx.y;          // 0..15
    const int tid = ty * 16 + tx;        // 0..255

    float acc[4][4];
#pragma unroll
    for (int i = 0; i < 4; i++)
#pragma unroll
        for (int j = 0; j < 4; j++) acc[i][j] = 0.f;

    for (int k0 = 0; k0 < K; k0 += BK) {
#pragma unroll
        for (int l = 0; l < 4; l++) {
            int idx = tid + l * 256;                 // 0..1023
            // A tile: 64 rows x 16 k
            int a_row = idx >> 4;
            int a_col = idx & 15;
            int gr = rowBase + a_row;
            int gk = k0 + a_col;
            float va = 0.f;
            if (gr < M) {
                if (CONCAT)
                    va = (gk < D) ? A0[(long long)gr * D + gk]
                                  : A1[(long long)gr * D + (gk - D)];
                else
                    va = A0[(long long)gr * K + gk];
            }
            As[a_col][a_row] = va;
            // B tile: 16 k x 64 cols (N=512, col always in range)
            int b_row = idx >> 6;
            int b_col = idx & 63;
            Bs[b_row][b_col] = B[(long long)(k0 + b_row) * N + colBase + b_col];
        }
        __syncthreads();

#pragma unroll
        for (int k = 0; k < BK; k++) {
            float a[4], b[4];
#pragma unroll
            for (int i = 0; i < 4; i++) a[i] = As[k][ty * 4 + i];
#pragma unroll
            for (int j = 0; j < 4; j++) b[j] = Bs[k][tx * 4 + j];
#pragma unroll
            for (int i = 0; i < 4; i++)
#pragma unroll
                for (int j = 0; j < 4; j++) acc[i][j] = fmaf(a[i], b[j], acc[i][j]);
        }
        __syncthreads();
    }

#pragma unroll
    for (int i = 0; i < 4; i++) {
        int r = rowBase + ty * 4 + i;
        if (r >= M) continue;
#pragma unroll
        for (int j = 0; j < 4; j++) {
            int cc = colBase + tx * 4 + j;
            float v = acc[i][j] + bias[cc];
            if (SILU) v = v / (1.f + expf(-v));
            C[(long long)r * N + cc] = v;
        }
    }
}

// ---------------- kernel 5: LayerNorm + residual ---------------------------
// one block (128 threads) per row; each thread owns 4 strided elements
__global__ void ln_res_kernel(const float* __restrict__ nfeat,
                              const float* __restrict__ ln_w,
                              const float* __restrict__ ln_b,
                              float*       __restrict__ out_n) {
    int row = blockIdx.x;
    int t = threadIdx.x;                // 0..127
    const float* h = &g_h2[(long long)row * D];

    float x[4], s = 0.f, ss = 0.f;
#pragma unroll
    for (int l = 0; l < 4; l++) {
        x[l] = h[t + l * 128];
        s += x[l];
        ss += x[l] * x[l];
    }
    // block reduction: warp shuffle + shared across 4 warps
    __shared__ float rs[4], rss[4], sm[2];
#pragma unroll
    for (int o = 16; o > 0; o >>= 1) {
        s  += __shfl_down_sync(0xFFFFFFFF, s,  o);
        ss += __shfl_down_sync(0xFFFFFFFF, ss, o);
    }
    int warp = t >> 5, lane = t & 31;
    if (lane == 0) { rs[warp] = s; rss[warp] = ss; }
    __syncthreads();
    if (t == 0) {
        float S = rs[0] + rs[1] + rs[2] + rs[3];
        float SS = rss[0] + rss[1] + rss[2] + rss[3];
        float mu = S / (float)D;
        float var = SS / (float)D - mu * mu;
        sm[0] = mu;
        sm[1] = rsqrtf(var + LN_EPS);
    }
    __syncthreads();
    float mu = sm[0], inv = sm[1];

#pragma unroll
    for (int l = 0; l < 4; l++) {
        int c = t + l * 128;
        float v = (x[l] - mu) * inv * ln_w[c] + ln_b[c]
                  + nfeat[(long long)row * D + c];
        out_n[(long long)row * D + c] = v;
    }
}

// ---------------- launch ----------------------------------------------------
extern "C" void kernel_launch(void* const* d_in, const int* in_sizes, int n_in,
                              void* d_out, int out_size) {
    const float* efeat = (const float*)d_in[0];   // [160000, 512]
    const float* nfeat = (const float*)d_in[1];   // [10000, 512]
    const void*  dst   = d_in[2];                 // [160000] int64 or int32
    const float* W1    = (const float*)d_in[3];   // [1024, 512]
    const float* b1    = (const float*)d_in[4];   // [512]
    const float* W2    = (const float*)d_in[5];   // [512, 512]
    const float* b2    = (const float*)d_in[6];   // [512]
    const float* ln_w  = (const float*)d_in[7];   // [512]
    const float* ln_b  = (const float*)d_in[8];   // [512]

    float* out   = (float*)d_out;
    float* out_e = out;                                      // [160000*512]
    float* out_n = out + (long long)N_EDGES * D;             // [10000*512]

    // 0) zero agg + flag
    {
        int total = (N_NODES * D) / 4;
        zero_kernel<<<(total + 255) / 256, 256>>>();
    }
    // 1) dst dtype probe
    probe_dst_kernel<<<(N_EDGES / 2 + 255) / 256, 256>>>((const int*)dst);
    // 2) fused efeat passthrough + scatter-add
    {
        long long total = (long long)N_EDGES * (D / 4);
        int blocks = (int)((total + 255) / 256);
        scatter_kernel<<<blocks, 256>>>((const float4*)efeat, dst,
                                        (float4*)out_e);
    }
    // 3) GEMM1: h1 = silu([agg|nfeat] @ W1 + b1)   (M=10000, N=512, K=1024)
    {
        dim3 grid(D / BN, (N_NODES + BM - 1) / BM);
        dim3 block(16, 16);
        float* aggp; cudaGetSymbolAddress((void**)&aggp, g_agg);
        float* h1p;  cudaGetSymbolAddress((void**)&h1p,  g_h1);
        gemm_kernel<true, true><<<grid, block>>>(aggp, nfeat, W1, b1, h1p,
                                                 N_NODES, D, D_CAT);
    }
    // 4) GEMM2: h2 = h1 @ W2 + b2                  (M=10000, N=512, K=512)
    {
        dim3 grid(D / BN, (N_NODES + BM - 1) / BM);
        dim3 block(16, 16);
        float* h1p; cudaGetSymbolAddress((void**)&h1p, g_h1);
        float* h2p; cudaGetSymbolAddress((void**)&h2p, g_h2);
        gemm_kernel<false, false><<<grid, block>>>(h1p, nullptr, W2, b2, h2p,
                                                   N_NODES, D, D);
    }
    // 5) LayerNorm + residual -> out_n
    ln_res_kernel<<<N_NODES, 128>>>(nfeat, ln_w, ln_b, out_n);
}

// round 7
// speedup vs baseline: 1.3984x; 1.3984x over previous
#include <cuda_runtime.h>
#include <cuda_bf16.h>
#include <math.h>

#define N_NODES 10000
#define N_EDGES 160000
#define D 512
#define D_CAT 1024
#define LN_EPS 1e-5f

// ---------------- scratch (device globals; no runtime allocation) ----------
__device__ float g_agg[N_NODES * D];   // 20.48 MB  segment-sum result
__device__ float g_h1 [N_NODES * D];   // 20.48 MB  silu(cat @ W1 + b1)
__device__ float g_h2 [N_NODES * D];   // 20.48 MB  h1 @ W2 + b2
__device__ int   g_dst_is32;           // 1 if dst buffer is int32, 0 if int64

// ---------------- kernel 0: zero agg + flag --------------------------------
__global__ void zero_kernel() {
    int i = blockIdx.x * blockDim.x + threadIdx.x;
    int total = (N_NODES * D) / 4;
    if (i == 0) g_dst_is32 = 0;
    if (i < total) {
        reinterpret_cast<float4*>(g_agg)[i] = make_float4(0.f, 0.f, 0.f, 0.f);
    }
}

// ---------------- kernel 1: dtype probe ------------------------------------
// View dst as int32[160000]. If true dtype is int64 (LE, values < 10000),
// every odd 32-bit word is zero; if int32, odd words are uniform dst values
// and some are nonzero with overwhelming probability.
__global__ void probe_dst_kernel(const int* __restrict__ dst32) {
    int i = blockIdx.x * blockDim.x + threadIdx.x;       // 0 .. 79999
    if (i < N_EDGES / 2) {
        if (dst32[2 * i + 1] != 0) g_dst_is32 = 1;       // racy all-write-1: fine
    }
}

// ---------------- kernel 2: fused efeat passthrough + scatter-add ----------
__global__ void scatter_kernel(const float4* __restrict__ efeat,
                               const void*  __restrict__ dst_raw,
                               float4*      __restrict__ out_efeat) {
    long long i = (long long)blockIdx.x * blockDim.x + threadIdx.x;
    long long total = (long long)N_EDGES * (D / 4);
    if (i >= total) return;
    int e = (int)(i >> 7);          // i / 128
    int c = (int)(i & 127);         // i % 128

    float4 v = efeat[i];
    out_efeat[i] = v;               // passthrough (single read of efeat)

    int node;
    if (g_dst_is32) node = ((const int*)dst_raw)[e];
    else            node = (int)((const long long*)dst_raw)[e];

    float* base = &g_agg[(long long)node * D + c * 4];
    // vector reduction (sm_90+): one L2 RMW op for 16 bytes
    asm volatile("red.global.v4.f32.add [%0], {%1, %2, %3, %4};"
                 :: "l"(base), "f"(v.x), "f"(v.y), "f"(v.z), "f"(v.w)
                 : "memory");
}

// ---------------- 128x128x8 register-blocked SGEMM -------------------------
// C[M,N] = op(A) @ B + bias, optional SiLU epilogue.
// CONCAT: logical A row = [A0 row (512) | A1 row (512)], K = 1024.
// 256 threads, 8x8 accumulators per thread, double-buffered smem,
// transposed A tile (As[k][m]) so the inner product is two LDS.128 per
// operand per k. One __syncthreads() per 8-deep k-slice.
template<bool CONCAT, bool SILU>
__global__ void __launch_bounds__(256, 2)
gemm128_kernel(const float* __restrict__ A0,
               const float* __restrict__ A1,
               const float* __restrict__ B,     // [K, N] row-major
               const float* __restrict__ bias,  // [N]
               float*       __restrict__ C,     // [M, N]
               int M, int N, int K) {
    __shared__ float As[2][8][128];
    __shared__ float Bs[2][8][128];

    const int tid = threadIdx.x;                 // 0..255
    const int rowBase = blockIdx.y * 128;
    const int colBase = blockIdx.x * 128;

    // global-load assignment: one float4 of A + one float4 of B per thread
    const int a_row = tid >> 1;                  // 0..127
    const int a_k   = (tid & 1) << 2;            // 0 or 4
    const int b_row = tid >> 5;                  // 0..7
    const int b_col = (tid & 31) << 2;           // 0..124

    // compute assignment: 8 rows x 8 cols per thread
    const int tx = tid & 15;
    const int ty = tid >> 4;
    const int m0 = ty * 8;
    const int n0 = tx * 8;

    float acc[8][8];
#pragma unroll
    for (int i = 0; i < 8; i++)
#pragma unroll
        for (int j = 0; j < 8; j++) acc[i][j] = 0.f;

    const int gr = rowBase + a_row;
    const bool a_ok = (gr < M);

    // --- tile load helpers ---
    auto ldA = [&](int k0) -> float4 {
        if (!a_ok) return make_float4(0.f, 0.f, 0.f, 0.f);
        int gk = k0 + a_k;
        if (CONCAT) {
            const float* src = (gk < D)
                ? (A0 + (long long)gr * D + gk)
                : (A1 + (long long)gr * D + (gk - D));
            return *reinterpret_cast<const float4*>(src);
        }
        return *reinterpret_cast<const float4*>(A0 + (long long)gr * K + gk);
    };
    auto ldB = [&](int k0) -> float4 {
        return *reinterpret_cast<const float4*>(
            B + (long long)(k0 + b_row) * N + colBase + b_col);
    };

    // preload slice 0
    {
        float4 ra = ldA(0);
        float4 rb = ldB(0);
        As[0][a_k + 0][a_row] = ra.x;
        As[0][a_k + 1][a_row] = ra.y;
        As[0][a_k + 2][a_row] = ra.z;
        As[0][a_k + 3][a_row] = ra.w;
        *reinterpret_cast<float4*>(&Bs[0][b_row][b_col]) = rb;
    }
    __syncthreads();

    const int nIter = K >> 3;
    int buf = 0;
    for (int it = 0; it < nIter; ++it) {
        float4 ra, rb;
        const bool has_next = (it + 1 < nIter);
        if (has_next) {
            ra = ldA((it + 1) << 3);
            rb = ldB((it + 1) << 3);
        }
#pragma unroll
        for (int k = 0; k < 8; ++k) {
            float4 a0 = *reinterpret_cast<const float4*>(&As[buf][k][m0]);
            float4 a1 = *reinterpret_cast<const float4*>(&As[buf][k][m0 + 4]);
            float4 b0 = *reinterpret_cast<const float4*>(&Bs[buf][k][n0]);
            float4 b1 = *reinterpret_cast<const float4*>(&Bs[buf][k][n0 + 4]);
            float a[8] = {a0.x, a0.y, a0.z, a0.w, a1.x, a1.y, a1.z, a1.w};
            float b[8] = {b0.x, b0.y, b0.z, b0.w, b1.x, b1.y, b1.z, b1.w};
#pragma unroll
            for (int i = 0; i < 8; i++)
#pragma unroll
                for (int j = 0; j < 8; j++)
                    acc[i][j] = fmaf(a[i], b[j], acc[i][j]);
        }
        if (has_next) {
            int nb = buf ^ 1;
            As[nb][a_k + 0][a_row] = ra.x;
            As[nb][a_k + 1][a_row] = ra.y;
            As[nb][a_k + 2][a_row] = ra.z;
            As[nb][a_k + 3][a_row] = ra.w;
            *reinterpret_cast<float4*>(&Bs[nb][b_row][b_col]) = rb;
            __syncthreads();
            buf = nb;
        }
    }

    // epilogue: bias (+ SiLU), vectorized stores
#pragma unroll
    for (int i = 0; i < 8; i++) {
        int r = rowBase + m0 + i;
        if (r >= M) continue;
        float* crow = C + (long long)r * N + colBase + n0;
#pragma unroll
        for (int jj = 0; jj < 8; jj += 4) {
            float4 o;
            float v0 = acc[i][jj + 0] + bias[colBase + n0 + jj + 0];
            float v1 = acc[i][jj + 1] + bias[colBase + n0 + jj + 1];
            float v2 = acc[i][jj + 2] + bias[colBase + n0 + jj + 2];
            float v3 = acc[i][jj + 3] + bias[colBase + n0 + jj + 3];
            if (SILU) {
                v0 = v0 / (1.f + expf(-v0));
                v1 = v1 / (1.f + expf(-v1));
                v2 = v2 / (1.f + expf(-v2));
                v3 = v3 / (1.f + expf(-v3));
            }
            o.x = v0; o.y = v1; o.z = v2; o.w = v3;
            *reinterpret_cast<float4*>(crow + jj) = o;
        }
    }
}

// ---------------- kernel 5: LayerNorm + residual ---------------------------
__global__ void ln_res_kernel(const float* __restrict__ nfeat,
                              const float* __restrict__ ln_w,
                              const float* __restrict__ ln_b,
                              float*       __restrict__ out_n) {
    int row = blockIdx.x;
    int t = threadIdx.x;                // 0..127
    const float* h = &g_h2[(long long)row * D];

    float x[4], s = 0.f, ss = 0.f;
#pragma unroll
    for (int l = 0; l < 4; l++) {
        x[l] = h[t + l * 128];
        s += x[l];
        ss += x[l] * x[l];
    }
    __shared__ float rs[4], rss[4], sm[2];
#pragma unroll
    for (int o = 16; o > 0; o >>= 1) {
        s  += __shfl_down_sync(0xFFFFFFFF, s,  o);
        ss += __shfl_down_sync(0xFFFFFFFF, ss, o);
    }
    int warp = t >> 5, lane = t & 31;
    if (lane == 0) { rs[warp] = s; rss[warp] = ss; }
    __syncthreads();
    if (t == 0) {
        float S  = rs[0] + rs[1] + rs[2] + rs[3];
        float SS = rss[0] + rss[1] + rss[2] + rss[3];
        float mu = S / (float)D;
        float var = SS / (float)D - mu * mu;
        sm[0] = mu;
        sm[1] = rsqrtf(var + LN_EPS);
    }
    __syncthreads();
    float mu = sm[0], inv = sm[1];

#pragma unroll
    for (int l = 0; l < 4; l++) {
        int c = t + l * 128;
        float v = (x[l] - mu) * inv * ln_w[c] + ln_b[c]
                  + nfeat[(long long)row * D + c];
        out_n[(long long)row * D + c] = v;
    }
}

// ---------------- launch ----------------------------------------------------
extern "C" void kernel_launch(void* const* d_in, const int* in_sizes, int n_in,
                              void* d_out, int out_size) {
    const float* efeat = (const float*)d_in[0];   // [160000, 512]
    const float* nfeat = (const float*)d_in[1];   // [10000, 512]
    const void*  dst   = d_in[2];                 // [160000] int64 or int32
    const float* W1    = (const float*)d_in[3];   // [1024, 512]
    const float* b1    = (const float*)d_in[4];   // [512]
    const float* W2    = (const float*)d_in[5];   // [512, 512]
    const float* b2    = (const float*)d_in[6];   // [512]
    const float* ln_w  = (const float*)d_in[7];   // [512]
    const float* ln_b  = (const float*)d_in[8];   // [512]

    float* out   = (float*)d_out;
    float* out_e = out;                                      // [160000*512]
    float* out_n = out + (long long)N_EDGES * D;             // [10000*512]

    // 0) zero agg + flag
    {
        int total = (N_NODES * D) / 4;
        zero_kernel<<<(total + 255) / 256, 256>>>();
    }
    // 1) dst dtype probe
    probe_dst_kernel<<<(N_EDGES / 2 + 255) / 256, 256>>>((const int*)dst);
    // 2) fused efeat passthrough + scatter-add
    {
        long long total = (long long)N_EDGES * (D / 4);
        int blocks = (int)((total + 255) / 256);
        scatter_kernel<<<blocks, 256>>>((const float4*)efeat, dst,
                                        (float4*)out_e);
    }
    float* aggp; cudaGetSymbolAddress((void**)&aggp, g_agg);
    float* h1p;  cudaGetSymbolAddress((void**)&h1p,  g_h1);
    float* h2p;  cudaGetSymbolAddress((void**)&h2p,  g_h2);
    // 3) GEMM1: h1 = silu([agg|nfeat] @ W1 + b1)   (M=10000, N=512, K=1024)
    {
        dim3 grid(D / 128, (N_NODES + 127) / 128);   // (4, 79)
        gemm128_kernel<true, true><<<grid, 256>>>(aggp, nfeat, W1, b1, h1p,
                                                  N_NODES, D, D_CAT);
    }
    // 4) GEMM2: h2 = h1 @ W2 + b2                  (M=10000, N=512, K=512)
    {
        dim3 grid(D / 128, (N_NODES + 127) / 128);
        gemm128_kernel<false, false><<<grid, 256>>>(h1p, nullptr, W2, b2, h2p,
                                                    N_NODES, D, D);
    }
    // 5) LayerNorm + residual -> out_n
    ln_res_kernel<<<N_NODES, 128>>>(nfeat, ln_w, ln_b, out_n);
}